// round 16
// baseline (speedup 1.0000x reference)
#include <cuda_runtime.h>

// Grouping: segment mean-pooling over sorted segment ids — single kernel,
// one CTA per 4 consecutive groups, one predicted window per CTA.
//   feats: [B=8, S=8192, H=512] f32;  seg: [B, S] i32 sorted
//   out:   grouped [B, G=1024, H] f32, then (if room) counts [B, G] as f32
//
// Groups are contiguous in tokens, so one contiguous id window around 8*g0 covers
// all 5 boundaries of groups g0..g0+3 (span ~32 tokens + 4-sigma slack). One window
// amortized over 4 groups cuts the R15 prologue cost ~4x; exact coverage check with
// warp-cooperative fallback keeps correctness unconditional.

#define BB 8
#define SS 8192
#define HH 512
#define GG 1024
#define H4 (HH / 4)   // 128 float4 per row == blockDim.x
#define GPC 4         // groups per CTA
#define QPB (GG / GPC)    // 256 quads per batch row
#define W  417        // window entries; entry i = token (8*g0 - 184 + i)

__device__ __forceinline__ int lower_bound_warp32(const int* __restrict__ row,
                                                  int target, int lane)
{
    int v = __ldg(row + lane * 256 + 255);
    unsigned m = __ballot_sync(0xffffffffu, v < target);
    int lo = __popc(m) * 256;
    if (lo == SS) return SS;
    v = __ldg(row + lo + lane * 8 + 7);
    m = __ballot_sync(0xffffffffu, v < target);
    lo += __popc(m) * 8;
    if (lo == SS) return SS;
    v = __ldg(row + lo + (lane & 7));
    m = __ballot_sync(0xffffffffu, (lane < 8) && (v < target));
    return lo + __popc(m);
}

__global__ __launch_bounds__(128, 16)
void group_mean_kernel(const float4* __restrict__ feats4,
                       const int* __restrict__ seg,
                       float* __restrict__ out,
                       int write_counts)
{
    const int bq = blockIdx.x;          // 0 .. B*QPB-1
    const int b  = bq >> 8;             // / QPB
    const int g0 = (bq & (QPB - 1)) * GPC;
    const int t  = threadIdx.x;

    __shared__ int sid[W];
    __shared__ int sh_bounds[GPC + 1];

    const int* __restrict__ srow = seg + b * SS;
    const int p0 = (g0 << 3) - 184;     // token position of sid[0]

    // contiguous, coalesced window load with edge sentinels
    #pragma unroll
    for (int k = 0; k < 4; ++k) {
        int i = t + k * 128;            // 0..511 >= W
        if (i < W) {
            int p = p0 + i;
            sid[i] = (p < 0) ? -1 : ((p >= SS) ? GG : srow[p]);
        }
    }
    __syncthreads();

    // exact coverage: boundaries of g0 and g0+GPC both strictly inside window
    const bool covered = (sid[0] < g0) && (sid[W - 1] >= g0 + GPC);

    if (covered) {
        // adjacent-diff: entry i is lower_bound for every target in (sid[i-1], sid[i]]
        #pragma unroll
        for (int k = 0; k < 4; ++k) {
            int i = t + k * 128 + 1;    // 1..W-1
            if (i < W) {
                int a = sid[i - 1], c = sid[i];
                int glo = max(a + 1, g0);
                int ghi = min(c, g0 + GPC);
                for (int tg = glo; tg <= ghi; ++tg)
                    sh_bounds[tg - g0] = p0 + i;
            }
        }
    } else {
        // rare: warp w searches target g0+w; warp 0 also does g0+GPC
        const int w = t >> 5, lane = t & 31;
        int r = lower_bound_warp32(srow, g0 + w, lane);
        if (lane == 0) sh_bounds[w] = r;
        if (w == 0) {
            int r2 = lower_bound_warp32(srow, g0 + GPC, lane);
            if (lane == 0) sh_bounds[GPC] = r2;
        }
    }
    __syncthreads();

    // ---- stream the 4 contiguous groups ----
    const float4* __restrict__ fb = feats4 + (size_t)b * SS * H4 + t;
    float4* __restrict__ ob = (float4*)out + ((size_t)b * GG + g0) * H4 + t;

    #pragma unroll
    for (int j = 0; j < GPC; ++j) {
        const int start = sh_bounds[j];
        const int cnt   = sh_bounds[j + 1] - start;

        float4 acc = make_float4(0.f, 0.f, 0.f, 0.f);
        const float4* __restrict__ p = fb + (size_t)start * H4;
        int s = 0;
        for (; s + 4 <= cnt; s += 4) {
            float4 v0 = p[(size_t)(s + 0) * H4];
            float4 v1 = p[(size_t)(s + 1) * H4];
            float4 v2 = p[(size_t)(s + 2) * H4];
            float4 v3 = p[(size_t)(s + 3) * H4];
            acc.x += (v0.x + v1.x) + (v2.x + v3.x);
            acc.y += (v0.y + v1.y) + (v2.y + v3.y);
            acc.z += (v0.z + v1.z) + (v2.z + v3.z);
            acc.w += (v0.w + v1.w) + (v2.w + v3.w);
        }
        for (; s < cnt; ++s) {
            float4 v = p[(size_t)s * H4];
            acc.x += v.x; acc.y += v.y; acc.z += v.z; acc.w += v.w;
        }

        const float inv = (cnt > 0) ? (1.0f / (float)cnt) : 0.0f;
        acc.x *= inv; acc.y *= inv; acc.z *= inv; acc.w *= inv;
        ob[(size_t)j * H4] = acc;

        if (write_counts && t == 0)
            out[(size_t)BB * GG * HH + b * GG + g0 + j] = (float)cnt;
    }
}

extern "C" void kernel_launch(void* const* d_in, const int* in_sizes, int n_in,
                              void* d_out, int out_size)
{
    const float4* feats4 = (const float4*)d_in[0];
    const int*    seg    = (const int*)d_in[1];
    float*        out    = (float*)d_out;

    const int grouped_elems = BB * GG * HH;               // 4,194,304
    const int write_counts  = (out_size >= grouped_elems + BB * GG) ? 1 : 0;

    group_mean_kernel<<<BB * QPB, 128>>>(feats4, seg, out, write_counts);
}

// round 17
// speedup vs baseline: 1.0523x; 1.0523x over previous
#include <cuda_runtime.h>

// Grouping: segment mean-pooling over sorted segment ids.
//   feats: [B=8, S=8192, H=512] f32;  seg: [B, S] i32 sorted
//   out:   grouped [B, G=1024, H] f32, then (if room) counts [B, G] as f32
//
// Two kernels, overlapped with Programmatic Dependent Launch:
//   1) boundaries_kernel (64 CTAs): int4 adjacent-diff fills g_starts[b][g]
//      (lower_bound of g). Unique writer per entry, no atomics.
//   2) group_mean_kernel (8192 CTAs, PDL secondary): pure streamer — identical to
//      the measured 71.8%-DRAM kernel — gated by cudaGridDependencySynchronize().
// Rationale: every in-CTA boundary prologue variant measured 55-62% DRAM; only the
// prologue-free streamer hits 72%. So precompute bounds and hide the launch gap.

#define BB 8
#define SS 8192
#define HH 512
#define GG 1024
#define H4 (HH / 4)  // 128 float4 per row == blockDim.x

// g_starts[b][g] = first token index with seg id >= g; g_starts[b][G] = S
__device__ int g_starts[BB][GG + 1];

__global__ __launch_bounds__(128)
void boundaries_kernel(const int* __restrict__ seg)
{
    // 64 CTAs: bid = row*8 + chunk; 128 threads x 8 tokens = 1024 tokens/CTA
    const int row  = blockIdx.x >> 3;
    const int tloc = (blockIdx.x & 7) * 1024 + threadIdx.x * 8;  // token idx in row
    const int* __restrict__ srow = seg + row * SS;

    const int4 a = *reinterpret_cast<const int4*>(srow + tloc);
    const int4 c = *reinterpret_cast<const int4*>(srow + tloc + 4);
    const int prev = (tloc == 0) ? -1 : srow[tloc - 1];

    int ids[8] = {a.x, a.y, a.z, a.w, c.x, c.y, c.z, c.w};
    int p = prev;
    #pragma unroll
    for (int k = 0; k < 8; ++k) {
        const int cur = ids[k];
        for (int g = p + 1; g <= cur; ++g)     // unique crossing -> unique writer
            g_starts[row][g] = tloc + k;
        p = cur;
    }
    if (tloc + 8 == SS) {                      // trailing empty groups + sentinel
        for (int g = p + 1; g <= GG; ++g)
            g_starts[row][g] = SS;
    }
}

__global__ __launch_bounds__(128, 16)
void group_mean_kernel(const float4* __restrict__ feats4,
                       float* __restrict__ out,
                       int write_counts)
{
    // PDL: block until the boundaries kernel (primary) has completed.
    cudaGridDependencySynchronize();

    const int bg = blockIdx.x;          // 0 .. B*G-1
    const int b  = bg >> 10;            // / G
    const int g  = bg & (GG - 1);       // % G
    const int t  = threadIdx.x;

    // converged loads (same address across CTA) -> single L2 transaction
    const int start = g_starts[b][g];
    const int end   = g_starts[b][g + 1];
    const int cnt   = end - start;

    float4 acc = make_float4(0.f, 0.f, 0.f, 0.f);
    const float4* __restrict__ p = feats4 + ((size_t)b * SS + start) * H4 + t;

    int s = 0;
    // 4 independent LDG.128 in flight per thread
    for (; s + 4 <= cnt; s += 4) {
        float4 v0 = p[(size_t)(s + 0) * H4];
        float4 v1 = p[(size_t)(s + 1) * H4];
        float4 v2 = p[(size_t)(s + 2) * H4];
        float4 v3 = p[(size_t)(s + 3) * H4];
        acc.x += (v0.x + v1.x) + (v2.x + v3.x);
        acc.y += (v0.y + v1.y) + (v2.y + v3.y);
        acc.z += (v0.z + v1.z) + (v2.z + v3.z);
        acc.w += (v0.w + v1.w) + (v2.w + v3.w);
    }
    for (; s < cnt; ++s) {
        float4 v = p[(size_t)s * H4];
        acc.x += v.x; acc.y += v.y; acc.z += v.z; acc.w += v.w;
    }

    const float inv = (cnt > 0) ? (1.0f / (float)cnt) : 0.0f;
    acc.x *= inv; acc.y *= inv; acc.z *= inv; acc.w *= inv;

    ((float4*)out)[(size_t)bg * H4 + t] = acc;

    if (write_counts && t == 0) {
        out[(size_t)BB * GG * HH + bg] = (float)cnt;
    }
}

extern "C" void kernel_launch(void* const* d_in, const int* in_sizes, int n_in,
                              void* d_out, int out_size)
{
    const float4* feats4 = (const float4*)d_in[0];
    const int*    seg    = (const int*)d_in[1];
    float*        out    = (float*)d_out;

    const int grouped_elems = BB * GG * HH;               // 4,194,304
    const int write_counts  = (out_size >= grouped_elems + BB * GG) ? 1 : 0;

    boundaries_kernel<<<64, 128>>>(seg);

    // Secondary launch with Programmatic Dependent Launch: overlaps this kernel's
    // launch/CTA-residency with the boundaries kernel; the device-side
    // cudaGridDependencySynchronize() provides the actual dependency.
    cudaLaunchConfig_t cfg = {};
    cfg.gridDim  = dim3(BB * GG);
    cfg.blockDim = dim3(128);
    cfg.stream   = 0;
    cudaLaunchAttribute attr[1];
    attr[0].id = cudaLaunchAttributeProgrammaticStreamSerialization;
    attr[0].val.programmaticStreamSerializationAllowed = 1;
    cfg.attrs    = attr;
    cfg.numAttrs = 1;
    cudaLaunchKernelEx(&cfg, group_mean_kernel, feats4, out, write_counts);
}